// round 15
// baseline (speedup 1.0000x reference)
#include <cuda_runtime.h>
#include <cuda_fp16.h>
#include <math.h>
#include <stdint.h>

// Problem constants
#define BSZ 128
#define PIX 196
#define EDIM 512
#define HDIM 512
#define ADIM 512
#define EMBD 512
#define VOC 32000
#define TT 20
#define ZROW 1536   // per-row: [ctx(512) | hn_slot0(512) | hn_slot1(512)]
#define G4 2048     // 4*H
#define KP 1536

// fp16 dual-split geometry (k16 steps)
#define NKS_M 64                // mixed sweep: A[hi|lo_s] x B[lo_s|hi], K''=1024
#define NKS_H 32                // hi sweep: K=512 (B read from mixed array hi-half)
#define NT8 (VOC / 8)           // 4000 vocab n-tiles
#define KA_MT (BSZ * PIX / 16)  // 1568 m-tiles for ka
#define KA_NT (ADIM / 8)        // 64 n-tiles for ka

// ---------------- device scratch ----------------
__device__ float g_mean[BSZ * EDIM];
__device__ float g_h[BSZ * HDIM];
__device__ float g_c[BSZ * HDIM];
__device__ float g_q[BSZ * ADIM];
__device__ float g_ctx[BSZ * EDIM];
__device__ float g_z[BSZ * ZROW];
__device__ float g_ka[BSZ * PIX * ADIM];            // 51.4 MB fp32
__device__ float g_Wcat[G4 * KP];
__device__ float g_bcat[G4];
__device__ float g_scratch[(size_t)BSZ * TT * VOC]; // 327 MB
__device__ unsigned long long g_amax2[2][BSZ];
// fp16 mma fragments
__device__ __half g_AfragM[8 * NKS_M * 32 * 8];            // logits A mixed (262 KB)
__device__ __half g_AfragH[8 * NKS_H * 32 * 8];            // logits A hi (131 KB)
__device__ __half g_BfragM[(size_t)NT8 * NKS_M * 32 * 4];  // logits B [lo_s|hi] 65.5 MB
__device__ __half g_AkaM[(size_t)KA_MT * NKS_M * 32 * 8];  // ka A mixed 51.4 MB
__device__ __half g_AkaH[(size_t)KA_MT * NKS_H * 32 * 8];  // ka A hi 25.7 MB
__device__ __half g_BkaM[(size_t)KA_NT * NKS_M * 32 * 4];  // ka B [lo_s|hi] 1 MB

#define LO_SCALE 2048.0f
#define LO_INV   (1.0f / 2048.0f)

__device__ __forceinline__ float sigmf(float x) { return 1.0f / (1.0f + expf(-x)); }

__device__ __forceinline__ unsigned long long amax_key(float v, int n) {
    unsigned u = __float_as_uint(v);
    u = (u & 0x80000000u) ? ~u : (u | 0x80000000u);
    return ((unsigned long long)u << 32) | (unsigned long long)(0xFFFFFFFFu - (unsigned)n);
}
__device__ __forceinline__ int amax_idx(unsigned long long key) {
    return (int)(0xFFFFFFFFu - (unsigned)(key & 0xFFFFFFFFull));
}

// ---- fp16 m16n8k16 A-fragment addressing ----
__device__ __forceinline__ void wrA16(__half* base, int nks, int m, int k, __half v) {
    const int mt = m >> 4, mr = m & 15;
    const int ks = k >> 4, kk = k & 15;
    const int lane = 4 * (mr & 7) + ((kk >> 1) & 3);
    const int reg = ((mr >= 8) ? 1 : 0) + ((kk >= 8) ? 2 : 0);
    base[(((size_t)mt * nks + ks) * 32 + lane) * 8 + reg * 2 + (kk & 1)] = v;
}
__device__ __forceinline__ void put_afrag(int m, int h, float v) {
    __half hi = __float2half(v);
    __half lo = __float2half((v - __half2float(hi)) * LO_SCALE);
    wrA16(g_AfragM, NKS_M, m, h, hi);
    wrA16(g_AfragM, NKS_M, m, 512 + h, lo);
    wrA16(g_AfragH, NKS_H, m, h, hi);
}

// ---------------- cp.async / mma helpers ----------------
__device__ __forceinline__ uint32_t smem_u32(const void* p) {
    uint32_t a;
    asm("{ .reg .u64 t; cvta.to.shared.u64 t, %1; cvt.u32.u64 %0, t; }" : "=r"(a) : "l"(p));
    return a;
}
__device__ __forceinline__ void cp16(uint32_t s, const void* g) {
    asm volatile("cp.async.cg.shared.global [%0], [%1], 16;" :: "r"(s), "l"(g));
}
__device__ __forceinline__ void cp8(uint32_t s, const void* g) {
    asm volatile("cp.async.ca.shared.global [%0], [%1], 8;" :: "r"(s), "l"(g));
}
__device__ __forceinline__ void cp_commit() {
    asm volatile("cp.async.commit_group;" ::: "memory");
}
template <int N>
__device__ __forceinline__ void cp_wait() {
    asm volatile("cp.async.wait_group %0;" :: "n"(N) : "memory");
}
__device__ __forceinline__ void mma_f16(float& c0, float& c1, float& c2, float& c3,
                                        uint32_t a0, uint32_t a1, uint32_t a2, uint32_t a3,
                                        uint32_t b0, uint32_t b1) {
    asm volatile(
        "mma.sync.aligned.m16n8k16.row.col.f32.f16.f16.f32 "
        "{%0,%1,%2,%3}, {%4,%5,%6,%7}, {%8,%9}, {%0,%1,%2,%3};"
        : "+f"(c0), "+f"(c1), "+f"(c2), "+f"(c3)
        : "r"(a0), "r"(a1), "r"(a2), "r"(a3), "r"(b0), "r"(b1));
}

// ================= shared fp16 mma sweep =================
// C[128 x 128] tile: A frags (8 mt) from Af/nksA, B frags (16 nt from nb0)/nksB.
#define L_STAGE_B 32768
#define L_SMEM 69632

__device__ void mma_sweep(char* sm, const uint4* __restrict__ Af, int nksA,
                          const uint2* __restrict__ Bf, int nksB,
                          int nchunk, int nb0, float c[4][4][4]) {
    const uint32_t sb32 = smem_u32(sm);
    const int tid = threadIdx.x;
    const int wid = tid >> 5, lane = tid & 31;
    const int warpM = wid >> 2, warpN = wid & 3;

    auto load_stage = [&](int cc) {
        const int ks0 = cc * 4;
        const uint32_t base = sb32 + (cc & 1) * L_STAGE_B;
#pragma unroll
        for (int i = 0; i < 4; i++) {          // A: 1024 x 16B
            const int idx = tid + i * 256;
            const int mt = idx >> 7, rem = idx & 127;
            const int ksl = rem >> 5, ln = rem & 31;
            cp16(base + idx * 16, Af + ((mt * nksA + ks0 + ksl) * 32 + ln));
        }
#pragma unroll
        for (int i = 0; i < 8; i++) {          // B: 2048 x 8B
            const int idx = tid + i * 256;
            const int ntl = idx >> 7;
            const int ksl = (idx >> 5) & 3, ln = idx & 31;
            cp8(base + 16384 + idx * 8,
                Bf + ((size_t)(nb0 + ntl) * nksB + ks0 + ksl) * 32 + ln);
        }
        cp_commit();
    };

    load_stage(0);
    for (int cc = 0; cc < nchunk; cc++) {
        if (cc + 1 < nchunk) { load_stage(cc + 1); cp_wait<1>(); }
        else                 { cp_wait<0>(); }
        __syncthreads();
        const char* buf = sm + (cc & 1) * L_STAGE_B;
#pragma unroll
        for (int ksl = 0; ksl < 4; ksl++) {
            uint4 af[4];
            uint2 bf[4];
#pragma unroll
            for (int mi = 0; mi < 4; mi++) {
                const int mt = warpM * 4 + mi;
                af[mi] = *(const uint4*)(buf + ((mt * 4 + ksl) * 32 + lane) * 16);
            }
#pragma unroll
            for (int ni = 0; ni < 4; ni++) {
                const int nt = warpN * 4 + ni;
                bf[ni] = *(const uint2*)(buf + 16384 + ((nt * 4 + ksl) * 32 + lane) * 8);
            }
#pragma unroll
            for (int mi = 0; mi < 4; mi++)
#pragma unroll
                for (int ni = 0; ni < 4; ni++)
                    mma_f16(c[mi][ni][0], c[mi][ni][1], c[mi][ni][2], c[mi][ni][3],
                            af[mi].x, af[mi].y, af[mi].z, af[mi].w,
                            bf[ni].x, bf[ni].y);
        }
        __syncthreads();
    }
}

__device__ __forceinline__ void stage_c(char* sm, float c[4][4][4]) {
    float* st = (float*)sm;                     // 128 x 132
    const int tid = threadIdx.x;
    const int wid = tid >> 5, lane = tid & 31;
    const int warpM = wid >> 2, warpN = wid & 3;
    const int g = lane >> 2, t4 = lane & 3;
#pragma unroll
    for (int mi = 0; mi < 4; mi++) {
        const int m = warpM * 64 + mi * 16 + g;
#pragma unroll
        for (int ni = 0; ni < 4; ni++) {
            const int col = warpN * 32 + ni * 8 + 2 * t4;
            st[m * 132 + col]           = c[mi][ni][0];
            st[m * 132 + col + 1]       = c[mi][ni][1];
            st[(m + 8) * 132 + col]     = c[mi][ni][2];
            st[(m + 8) * 132 + col + 1] = c[mi][ni][3];
        }
    }
}

// ================= fp16 dual-split logits GEMM =================
__global__ void __launch_bounds__(256, 2)
logits_mma(const float* __restrict__ bias, int t) {
    extern __shared__ char sm[];
    const int tid = threadIdx.x;
    const int nb0 = blockIdx.x * 16;
    const int n0 = blockIdx.x * 128;

    float c[4][4][4];
#pragma unroll
    for (int mi = 0; mi < 4; mi++)
#pragma unroll
        for (int ni = 0; ni < 4; ni++)
#pragma unroll
            for (int r = 0; r < 4; r++) c[mi][ni][r] = 0.0f;

    mma_sweep(sm, (const uint4*)g_AfragM, NKS_M,
              (const uint2*)g_BfragM, NKS_M, NKS_M / 4, nb0, c);
#pragma unroll
    for (int mi = 0; mi < 4; mi++)
#pragma unroll
        for (int ni = 0; ni < 4; ni++)
#pragma unroll
            for (int r = 0; r < 4; r++) c[mi][ni][r] *= LO_INV;
    // hi sweep: B = hi-half of BfragM (ks 32..63) via +32*32 uint2 offset
    mma_sweep(sm, (const uint4*)g_AfragH, NKS_H,
              (const uint2*)g_BfragM + 1024, NKS_M, NKS_H / 4, nb0, c);

    stage_c(sm, c);
    __syncthreads();
    float* st = (float*)sm;
    {
        const int row = tid & 127;
        const int c0 = (tid >> 7) * 64;
        float bestv = -3.4e38f;
        int bestn = 0;
#pragma unroll 8
        for (int cc2 = 0; cc2 < 64; cc2++) {
            const int col = c0 + cc2;
            float v = st[row * 132 + col] + __ldg(&bias[n0 + col]);
            if (v > bestv) { bestv = v; bestn = n0 + col; }
        }
        atomicMax(&g_amax2[t & 1][row], amax_key(bestv, bestn));
    }
    for (int idx = tid; idx < 128 * 128; idx += 256) {
        const int m2 = idx >> 7, cc2 = idx & 127;
        g_scratch[((size_t)m2 * TT + t) * VOC + n0 + cc2] =
            st[m2 * 132 + cc2] + __ldg(&bias[n0 + cc2]);
    }
}

// ================= fp16 dual-split ka GEMM =================
// ka[by*128..+128, n0..+128] = feature-tile @ W_ienc^T + b_ienc
__global__ void __launch_bounds__(256, 2)
ka_mma(const float* __restrict__ bias) {
    extern __shared__ char sm[];
    const int tid = threadIdx.x;
    const int nb0 = blockIdx.x * 16;
    const int n0 = blockIdx.x * 128;
    const int by = blockIdx.y;

    float c[4][4][4];
#pragma unroll
    for (int mi = 0; mi < 4; mi++)
#pragma unroll
        for (int ni = 0; ni < 4; ni++)
#pragma unroll
            for (int r = 0; r < 4; r++) c[mi][ni][r] = 0.0f;

    const uint4* AfM = (const uint4*)g_AkaM + (size_t)by * 8 * NKS_M * 32;
    const uint4* AfH = (const uint4*)g_AkaH + (size_t)by * 8 * NKS_H * 32;
    mma_sweep(sm, AfM, NKS_M, (const uint2*)g_BkaM, NKS_M, NKS_M / 4, nb0, c);
#pragma unroll
    for (int mi = 0; mi < 4; mi++)
#pragma unroll
        for (int ni = 0; ni < 4; ni++)
#pragma unroll
            for (int r = 0; r < 4; r++) c[mi][ni][r] *= LO_INV;
    mma_sweep(sm, AfH, NKS_H, (const uint2*)g_BkaM + 1024, NKS_M, NKS_H / 4, nb0, c);

    stage_c(sm, c);
    __syncthreads();
    const float* st = (const float*)sm;
    for (int idx = tid; idx < 128 * 128; idx += 256) {
        const int m2 = idx >> 7, cc2 = idx & 127;
        g_ka[((size_t)by * 128 + m2) * ADIM + n0 + cc2] =
            st[m2 * 132 + cc2] + __ldg(&bias[n0 + cc2]);
    }
}

// ===== coalesced B-fragment build (shared by logits W_out and ka W_ienc) =====
// dst layout [nt][ks<64][lane][4 halves]; ks<32 -> lo_s(W[k]), ks>=32 -> hi(W[k-512])
__global__ void k_bfrag(const float* __restrict__ W, __half* __restrict__ dst,
                        size_t nslots) {
    size_t s = (size_t)blockIdx.x * 256 + threadIdx.x;
    if (s >= nslots) return;
    const int lane = (int)(s & 31);
    const int ks = (int)((s >> 5) & 63);
    const int nt = (int)(s >> 11);
    const int n = nt * 8 + (lane >> 2);
    const bool isLo = (ks < 32);
    const int k0 = (ks & 31) * 16 + (lane & 3) * 2;
    const float* Wr = W + (size_t)n * 512;
    float w0 = __ldg(Wr + k0),     w1 = __ldg(Wr + k0 + 1);
    float w8 = __ldg(Wr + k0 + 8), w9 = __ldg(Wr + k0 + 9);
    auto cv = [&](float w) -> __half {
        __half hi = __float2half(w);
        return isLo ? __float2half((w - __half2float(hi)) * LO_SCALE) : hi;
    };
    __half2* d = (__half2*)(dst + s * 4);
    d[0] = __halves2half2(cv(w0), cv(w1));
    d[1] = __halves2half2(cv(w8), cv(w9));
}

// ===== coalesced A-fragment build for feature (ka) =====
// Mixed slots: [mt<1568][ks<64][lane][8 halves]; ks<32 -> hi(feat[k]), else lo_s.
// ks<32 slots also mirrored into the H array at [mt][ks<32][lane].
__global__ void k_afragKA(const float* __restrict__ F) {
    size_t s = (size_t)blockIdx.x * 256 + threadIdx.x;
    if (s >= (size_t)KA_MT * NKS_M * 32) return;
    const int lane = (int)(s & 31);
    const int ks = (int)((s >> 5) & 63);
    const int mt = (int)(s >> 11);
    const int r = lane >> 2;
    const int c0 = (lane & 3) * 2;
    const int bk = (ks & 31) * 16;
    const bool isHi = (ks < 32);
    const int m0 = mt * 16 + r;
    const float* F0 = F + (size_t)m0 * 512 + bk;        // row r
    const float* F1 = F0 + (size_t)8 * 512;             // row r+8
    float a0 = __ldg(F0 + c0),     a1 = __ldg(F0 + c0 + 1);
    float a8 = __ldg(F0 + c0 + 8), a9 = __ldg(F0 + c0 + 9);
    float b0 = __ldg(F1 + c0),     b1 = __ldg(F1 + c0 + 1);
    float b8 = __ldg(F1 + c0 + 8), b9 = __ldg(F1 + c0 + 9);
    auto cv = [&](float w) -> __half {
        __half hi = __float2half(w);
        return isHi ? hi : __float2half((w - __half2float(hi)) * LO_SCALE);
    };
    // halves order: [r,c0],[r,c0+1],[r+8,c0],[r+8,c0+1],[r,c0+8],[r,c0+9],[r+8,c0+8],[r+8,c0+9]
    __half2 h0 = __halves2half2(cv(a0), cv(a1));
    __half2 h1 = __halves2half2(cv(b0), cv(b1));
    __half2 h2 = __halves2half2(cv(a8), cv(a9));
    __half2 h3 = __halves2half2(cv(b8), cv(b9));
    __half2* dM = (__half2*)(g_AkaM + s * 8);
    dM[0] = h0; dM[1] = h1; dM[2] = h2; dM[3] = h3;
    if (isHi) {
        __half2* dH = (__half2*)(g_AkaH + (((size_t)mt * NKS_H + ks) * 32 + lane) * 8);
        dH[0] = h0; dH[1] = h1; dH[2] = h2; dH[3] = h3;
    }
}

// ================= K-split-2 small-M GEMM (256 threads) =================
// MODE 0: C = acc + bias   MODE 1: gated ctx   MODE 2: gates+cell   MODE 4: init hn
template <int MODE>
__global__ __launch_bounds__(256)
void gemm_ks(const float* __restrict__ A, const float* __restrict__ B,
             const float* __restrict__ bias, float* __restrict__ C,
             int N, int K,
             const float* __restrict__ emb,
             const unsigned long long* __restrict__ am_rd,
             unsigned long long* __restrict__ am_clr,
             int rd_par, int wr_par) {
    __shared__ float As[2][2][32][16];
    __shared__ float Bs[2][2][32][64];
    __shared__ float red[128][8];
    const int bn = blockIdx.x * 64;
    const int bm = blockIdx.y * 16;
    const int tid = threadIdx.x;
    const int l = tid & 127;
    const int g = tid >> 7;
    const int tx = l & 15;
    const int ty = l >> 4;
    const int ar = l >> 3;
    const int ac = (l & 7) * 4;
    const int br = l >> 1;
    const int bc = (l & 1) * 16;
    const int arow = bm + ar;
    const int kbase = g * (K >> 1);

    size_t tokoff = 0;
    if (MODE == 2) tokoff = (size_t)amax_idx(am_rd[arow]) * EMBD;
    const int hn_rd = 512 + rd_par * 512;

    const float* Bp = B + (size_t)(bn + br) * K + kbase + bc;

    auto ldA4 = [&](int k0) -> float4 {
        const int kk = kbase + k0 + ac;
        if (MODE == 2) {
            const float* p;
            if (kk < 512)       p = emb + tokoff + kk;
            else if (kk < 1024) p = g_z + (size_t)arow * ZROW + (kk - 512);
            else                p = g_z + (size_t)arow * ZROW + hn_rd + (kk - 1024);
            return *(const float4*)p;
        }
        return *(const float4*)(A + (size_t)arow * K + kk);
    };

    float4 av = ldA4(0);
    float4 bv0 = *(const float4*)(Bp + 0);
    float4 bv1 = *(const float4*)(Bp + 4);
    float4 bv2 = *(const float4*)(Bp + 8);
    float4 bv3 = *(const float4*)(Bp + 12);

    float acc[2][4] = {};
    const int nk = K >> 6;
    for (int it = 0; it < nk; it++) {
        const int st = it & 1;
        As[g][st][ac + 0][ar] = av.x; As[g][st][ac + 1][ar] = av.y;
        As[g][st][ac + 2][ar] = av.z; As[g][st][ac + 3][ar] = av.w;
        Bs[g][st][bc +  0][br] = bv0.x; Bs[g][st][bc +  1][br] = bv0.y;
        Bs[g][st][bc +  2][br] = bv0.z; Bs[g][st][bc +  3][br] = bv0.w;
        Bs[g][st][bc +  4][br] = bv1.x; Bs[g][st][bc +  5][br] = bv1.y;
        Bs[g][st][bc +  6][br] = bv1.z; Bs[g][st][bc +  7][br] = bv1.w;
        Bs[g][st][bc +  8][br] = bv2.x; Bs[g][st][bc +  9][br] = bv2.y;
        Bs[g][st][bc + 10][br] = bv2.z; Bs[g][st][bc + 11][br] = bv2.w;
        Bs[g][st][bc + 12][br] = bv3.x; Bs[g][st][bc + 13][br] = bv3.y;
        Bs[g][st][bc + 14][br] = bv3.z; Bs[g][st][bc + 15][br] = bv3.w;
        __syncthreads();
        if (it + 1 < nk) {
            const int k0 = (it + 1) << 5;
            av = ldA4(k0);
            bv0 = *(const float4*)(Bp + k0);
            bv1 = *(const float4*)(Bp + k0 + 4);
            bv2 = *(const float4*)(Bp + k0 + 8);
            bv3 = *(const float4*)(Bp + k0 + 12);
        }
#pragma unroll
        for (int k = 0; k < 32; k++) {
            float a0 = As[g][st][k][2 * ty];
            float a1 = As[g][st][k][2 * ty + 1];
            float4 bv = *(const float4*)(&Bs[g][st][k][tx * 4]);
            acc[0][0] = fmaf(a0, bv.x, acc[0][0]);
            acc[0][1] = fmaf(a0, bv.y, acc[0][1]);
            acc[0][2] = fmaf(a0, bv.z, acc[0][2]);
            acc[0][3] = fmaf(a0, bv.w, acc[0][3]);
            acc[1][0] = fmaf(a1, bv.x, acc[1][0]);
            acc[1][1] = fmaf(a1, bv.y, acc[1][1]);
            acc[1][2] = fmaf(a1, bv.z, acc[1][2]);
            acc[1][3] = fmaf(a1, bv.w, acc[1][3]);
        }
    }

    if (g == 1) {
#pragma unroll
        for (int r = 0; r < 2; r++)
#pragma unroll
            for (int j = 0; j < 4; j++) red[l][r * 4 + j] = acc[r][j];
    }
    __syncthreads();
    if (g != 0) return;
#pragma unroll
    for (int r = 0; r < 2; r++)
#pragma unroll
        for (int j = 0; j < 4; j++) acc[r][j] += red[l][r * 4 + j];

    const int m0 = bm + 2 * ty;
    const int n0 = bn + 4 * tx;
#pragma unroll
    for (int r = 0; r < 2; r++) {
        const int m = m0 + r;
        if (MODE == 2) {
            const int h = n0 >> 2;
            float gi = acc[r][0] + g_bcat[n0];
            float gf = acc[r][1] + g_bcat[n0 + 1];
            float gg = acc[r][2] + g_bcat[n0 + 2];
            float go = acc[r][3] + g_bcat[n0 + 3];
            float c = sigmf(gf) * g_c[m * HDIM + h] + sigmf(gi) * tanhf(gg);
            float hn = sigmf(go) * tanhf(c);
            g_c[m * HDIM + h] = c;
            g_h[m * HDIM + h] = hn;
            g_z[m * ZROW + 512 + wr_par * 512 + h] = hn;
            put_afrag(m, h, hn);
            if (blockIdx.x == 0 && tx == 0) am_clr[m] = 0ull;
        } else {
#pragma unroll
            for (int j = 0; j < 4; j++) {
                const int n = n0 + j;
                float v = acc[r][j] + bias[n];
                if (MODE == 0) {
                    C[(size_t)m * N + n] = v;
                } else if (MODE == 1) {
                    float s = sigmf(v);
                    g_z[m * ZROW + n] = s * g_ctx[m * 512 + n];
                } else if (MODE == 4) {
                    C[(size_t)m * N + n] = v;
                    g_z[m * ZROW + 512 + n] = v;
                    put_afrag(m, n, v);
                }
            }
        }
    }
}

// ---------------- small kernels ----------------
__global__ void k_mean(const float* __restrict__ feat) {
    int b = blockIdx.x, e = threadIdx.x;
    const float* f = feat + (size_t)b * PIX * EDIM + e;
    float s = 0.0f;
    for (int p = 0; p < PIX; p++) s += f[(size_t)p * EDIM];
    g_mean[b * EDIM + e] = s * (1.0f / (float)PIX);
}

__global__ void k_x0(const int* __restrict__ captions) {
    int b = threadIdx.x;
    g_amax2[1][b] = amax_key(0.0f, captions[b * TT]);
}

__global__ void k_pack(const float* __restrict__ Wlih, const float* __restrict__ Wlhh,
                       const float* __restrict__ blih, const float* __restrict__ blhh) {
    int i = blockIdx.x * blockDim.x + threadIdx.x;
    if (i >= G4 * KP) return;
    int jp = i / KP, k = i - jp * KP;
    int h = jp >> 2, gate = jp & 3;
    int orig = gate * 512 + h;
    g_Wcat[i] = (k < 1024) ? Wlih[(size_t)orig * 1024 + k]
                           : Wlhh[(size_t)orig * 512 + (k - 1024)];
    if (k == 0) g_bcat[jp] = blih[orig] + blhh[orig];
}

__global__ __launch_bounds__(512)
void k_att(const float* __restrict__ feat, const float* __restrict__ Watt,
           const float* __restrict__ batt) {
    __shared__ float q_s[ADIM];
    __shared__ float w_s[ADIM];
    __shared__ float e_s[PIX];
    __shared__ float red[16];
    const int b = blockIdx.x, tid = threadIdx.x;
    const int warp = tid >> 5, lane = tid & 31;

    q_s[tid] = g_q[b * ADIM + tid];
    w_s[tid] = Watt[tid];
    __syncthreads();

    for (int p = warp; p < PIX; p += 16) {
        const float* kap = g_ka + ((size_t)(b * PIX + p)) * ADIM;
        float s = 0.0f;
        for (int a = lane; a < ADIM; a += 32) {
            float v = kap[a] + q_s[a];
            s += fmaxf(v, 0.0f) * w_s[a];
        }
#pragma unroll
        for (int o = 16; o; o >>= 1) s += __shfl_xor_sync(0xffffffffu, s, o);
        if (lane == 0) e_s[p] = s + batt[0];
    }
    __syncthreads();

    float m = (tid < PIX) ? e_s[tid] : -3.4e38f;
#pragma unroll
    for (int o = 16; o; o >>= 1) m = fmaxf(m, __shfl_xor_sync(0xffffffffu, m, o));
    if (lane == 0) red[warp] = m;
    __syncthreads();
    if (tid == 0) {
        float v = red[0];
        for (int i = 1; i < 16; i++) v = fmaxf(v, red[i]);
        red[0] = v;
    }
    __syncthreads();
    m = red[0];
    float ex = (tid < PIX) ? expf(e_s[tid] - m) : 0.0f;
    float ssum = ex;
#pragma unroll
    for (int o = 16; o; o >>= 1) ssum += __shfl_xor_sync(0xffffffffu, ssum, o);
    __syncthreads();
    if (lane == 0) red[warp] = ssum;
    __syncthreads();
    if (tid == 0) {
        float v = 0.0f;
        for (int i = 0; i < 16; i++) v += red[i];
        red[0] = 1.0f / v;
    }
    __syncthreads();
    if (tid < PIX) e_s[tid] = ex * red[0];
    __syncthreads();

    float acc = 0.0f;
    const float* fb = feat + (size_t)b * PIX * EDIM + tid;
    for (int p = 0; p < PIX; p++) acc = fmaf(e_s[p], fb[(size_t)p * EDIM], acc);
    g_ctx[b * EDIM + tid] = acc;
}

__global__ __launch_bounds__(256)
void k_tr(float* __restrict__ out) {
    __shared__ float sm[256 * 21];
    const int b = blockIdx.y;
    const int v0 = blockIdx.x * 256;
    const int tid = threadIdx.x;
    const float* src = g_scratch + (size_t)b * TT * VOC;
#pragma unroll
    for (int t = 0; t < TT; t++) sm[tid * 21 + t] = src[(size_t)t * VOC + v0 + tid];
    __syncthreads();
    float* ob = out + (size_t)b * VOC * TT + (size_t)v0 * TT;
    for (int e = tid; e < 256 * TT; e += 256) {
        int v = e / TT, t = e - v * TT;
        ob[e] = sm[v * 21 + t];
    }
}

// ---------------- host launch ----------------
static inline void* sym_addr(const void* symbol) {
    void* p = nullptr;
    cudaGetSymbolAddress(&p, symbol);
    return p;
}

extern "C" void kernel_launch(void* const* d_in, const int* in_sizes, int n_in,
                              void* d_out, int out_size) {
    const float* feat    = (const float*)d_in[0];
    const int*   caps    = (const int*)d_in[1];
    const float* W_ienc  = (const float*)d_in[2];
    const float* b_ienc  = (const float*)d_in[3];
    const float* W_oenc  = (const float*)d_in[4];
    const float* b_oenc  = (const float*)d_in[5];
    const float* W_att   = (const float*)d_in[6];
    const float* b_att   = (const float*)d_in[7];
    const float* W_inith = (const float*)d_in[8];
    const float* b_inith = (const float*)d_in[9];
    const float* W_initc = (const float*)d_in[10];
    const float* b_initc = (const float*)d_in[11];
    const float* W_gate  = (const float*)d_in[12];
    const float* b_gate  = (const float*)d_in[13];
    const float* embT    = (const float*)d_in[14];
    const float* W_lih   = (const float*)d_in[15];
    const float* W_lhh   = (const float*)d_in[16];
    const float* b_lih   = (const float*)d_in[17];
    const float* b_lhh   = (const float*)d_in[18];
    const float* W_out   = (const float*)d_in[19];
    const float* b_out   = (const float*)d_in[20];
    float* out = (float*)d_out;

    float* p_mean = (float*)sym_addr(g_mean);
    float* p_h    = (float*)sym_addr(g_h);
    float* p_c    = (float*)sym_addr(g_c);
    float* p_q    = (float*)sym_addr(g_q);
    float* p_ctx  = (float*)sym_addr(g_ctx);
    float* p_Wcat = (float*)sym_addr(g_Wcat);
    __half* p_BfragM = (__half*)sym_addr(g_BfragM);
    __half* p_BkaM   = (__half*)sym_addr(g_BkaM);
    unsigned long long* p_am = (unsigned long long*)sym_addr(g_amax2);

    static cudaStream_t s1 = nullptr;
    static cudaEvent_t evRoot, evK;
    if (!s1) {
        cudaFuncSetAttribute(logits_mma, cudaFuncAttributeMaxDynamicSharedMemorySize, L_SMEM);
        cudaFuncSetAttribute(ka_mma,     cudaFuncAttributeMaxDynamicSharedMemorySize, L_SMEM);
        cudaStreamCreateWithFlags(&s1, cudaStreamNonBlocking);
        cudaEventCreateWithFlags(&evRoot, cudaEventDisableTiming);
        cudaEventCreateWithFlags(&evK,    cudaEventDisableTiming);
    }

    const dim3 gsQ(ADIM / 64, BSZ / 16);   // 64 blocks
    const dim3 gsG(G4 / 64, BSZ / 16);     // 256 blocks

    // ---- side stream: fp16-split ka (frag prep + mma) ----
    cudaEventRecord(evRoot, 0);
    cudaStreamWaitEvent(s1, evRoot, 0);
    {
        size_t nA = (size_t)KA_MT * NKS_M * 32;      // 3.2M slots
        size_t nBk = (size_t)KA_NT * NKS_M * 32;     // 131K slots
        k_afragKA<<<(unsigned)((nA + 255) / 256), 256, 0, s1>>>(feat);
        k_bfrag<<<(unsigned)((nBk + 255) / 256), 256, 0, s1>>>(W_ienc, p_BkaM, nBk);
        ka_mma<<<dim3(ADIM / 128, BSZ * PIX / 128), 256, L_SMEM, s1>>>(b_ienc);
    }
    cudaEventRecord(evK, s1);

    // ---- main-stream setup ----
    k_mean<<<BSZ, 512>>>(feat);
    gemm_ks<4><<<gsQ, 256>>>(p_mean, W_inith, b_inith, p_h, HDIM, EDIM,
                             nullptr, nullptr, nullptr, 0, 0);
    gemm_ks<0><<<gsQ, 256>>>(p_mean, W_initc, b_initc, p_c, HDIM, EDIM,
                             nullptr, nullptr, nullptr, 0, 0);
    k_x0<<<1, 128>>>(caps);
    k_pack<<<(G4 * KP + 255) / 256, 256>>>(W_lih, W_lhh, b_lih, b_lhh);
    {
        size_t nB = (size_t)NT8 * NKS_M * 32;        // 8.19M slots
        k_bfrag<<<(unsigned)((nB + 255) / 256), 256>>>(W_out, p_BfragM, nB);
    }

    cudaStreamWaitEvent(0, evK, 0);   // att needs ka; rejoins s1

    // ---- T recurrent steps ----
    for (int t = 0; t < TT; t++) {
        gemm_ks<0><<<gsQ, 256>>>(p_h, W_oenc, b_oenc, p_q, ADIM, HDIM,
                                 nullptr, nullptr, nullptr, 0, 0);
        k_att<<<BSZ, 512>>>(feat, W_att, b_att);
        gemm_ks<1><<<gsQ, 256>>>(p_ctx, W_gate, b_gate, nullptr, EDIM, EDIM,
                                 nullptr, nullptr, nullptr, 0, 0);
        gemm_ks<2><<<gsG, 256>>>(nullptr, p_Wcat, nullptr, nullptr, G4, KP, embT,
                                 p_am + ((t + 1) & 1) * BSZ, p_am + (t & 1) * BSZ,
                                 t & 1, (t + 1) & 1);
        logits_mma<<<VOC / 128, 256, L_SMEM>>>(b_out, t);
    }

    k_tr<<<dim3(VOC / 256, BSZ), 256>>>(out);
}

// round 16
// speedup vs baseline: 1.0072x; 1.0072x over previous
#include <cuda_runtime.h>
#include <cuda_fp16.h>
#include <math.h>
#include <stdint.h>

// Problem constants
#define BSZ 128
#define PIX 196
#define EDIM 512
#define HDIM 512
#define ADIM 512
#define EMBD 512
#define VOC 32000
#define TT 20
#define ZROW 1536   // per-row: [ctx(512) | hn_slot0(512) | hn_slot1(512)]
#define G4 2048     // 4*H
#define KP 1536

// fp16 dual-split geometry (k16 steps)
#define NKS_M 64                // mixed sweep: A[hi|lo_s] x B[lo_s|hi], K''=1024
#define NKS_H 32                // hi sweep: K=512 (B read from mixed array hi-half)
#define NT8 (VOC / 8)           // 4000 vocab n-tiles
#define KA_MT (BSZ * PIX / 16)  // 1568 m-tiles for ka
#define KA_NT (ADIM / 8)        // 64 n-tiles for ka

// ---------------- device scratch ----------------
__device__ float g_mean[BSZ * EDIM];
__device__ float g_h[BSZ * HDIM];
__device__ float g_c[BSZ * HDIM];
__device__ float g_q[BSZ * ADIM];
__device__ float g_ctx[BSZ * EDIM];
__device__ float g_z[BSZ * ZROW];
__device__ float g_ka[BSZ * PIX * ADIM];            // 51.4 MB fp32
__device__ float g_Wcat[G4 * KP];
__device__ float g_bcat[G4];
__device__ float g_scratch[(size_t)BSZ * TT * VOC]; // 327 MB
__device__ unsigned long long g_amax2[2][BSZ];
// fp16 mma fragments
__device__ __half g_AfragM[8 * NKS_M * 32 * 8];            // logits A mixed (262 KB)
__device__ __half g_AfragH[8 * NKS_H * 32 * 8];            // logits A hi (131 KB)
__device__ __half g_BfragM[(size_t)NT8 * NKS_M * 32 * 4];  // logits B [lo_s|hi] 65.5 MB
__device__ __half g_AkaM[(size_t)KA_MT * NKS_M * 32 * 8];  // ka A mixed 51.4 MB
__device__ __half g_AkaH[(size_t)KA_MT * NKS_H * 32 * 8];  // ka A hi 25.7 MB
__device__ __half g_BkaM[(size_t)KA_NT * NKS_M * 32 * 4];  // ka B [lo_s|hi] 1 MB

#define LO_SCALE 2048.0f
#define LO_INV   (1.0f / 2048.0f)

__device__ __forceinline__ float sigmf(float x) { return 1.0f / (1.0f + expf(-x)); }

__device__ __forceinline__ unsigned long long amax_key(float v, int n) {
    unsigned u = __float_as_uint(v);
    u = (u & 0x80000000u) ? ~u : (u | 0x80000000u);
    return ((unsigned long long)u << 32) | (unsigned long long)(0xFFFFFFFFu - (unsigned)n);
}
__device__ __forceinline__ int amax_idx(unsigned long long key) {
    return (int)(0xFFFFFFFFu - (unsigned)(key & 0xFFFFFFFFull));
}

// ---- fp16 m16n8k16 A-fragment addressing ----
__device__ __forceinline__ void wrA16(__half* base, int nks, int m, int k, __half v) {
    const int mt = m >> 4, mr = m & 15;
    const int ks = k >> 4, kk = k & 15;
    const int lane = 4 * (mr & 7) + ((kk >> 1) & 3);
    const int reg = ((mr >= 8) ? 1 : 0) + ((kk >= 8) ? 2 : 0);
    base[(((size_t)mt * nks + ks) * 32 + lane) * 8 + reg * 2 + (kk & 1)] = v;
}
__device__ __forceinline__ void put_afrag(int m, int h, float v) {
    __half hi = __float2half(v);
    __half lo = __float2half((v - __half2float(hi)) * LO_SCALE);
    wrA16(g_AfragM, NKS_M, m, h, hi);
    wrA16(g_AfragM, NKS_M, m, 512 + h, lo);
    wrA16(g_AfragH, NKS_H, m, h, hi);
}

// ---------------- cp.async / mma helpers ----------------
__device__ __forceinline__ uint32_t smem_u32(const void* p) {
    uint32_t a;
    asm("{ .reg .u64 t; cvta.to.shared.u64 t, %1; cvt.u32.u64 %0, t; }" : "=r"(a) : "l"(p));
    return a;
}
__device__ __forceinline__ void cp16(uint32_t s, const void* g) {
    asm volatile("cp.async.cg.shared.global [%0], [%1], 16;" :: "r"(s), "l"(g));
}
__device__ __forceinline__ void cp8(uint32_t s, const void* g) {
    asm volatile("cp.async.ca.shared.global [%0], [%1], 8;" :: "r"(s), "l"(g));
}
__device__ __forceinline__ void cp_commit() {
    asm volatile("cp.async.commit_group;" ::: "memory");
}
template <int N>
__device__ __forceinline__ void cp_wait() {
    asm volatile("cp.async.wait_group %0;" :: "n"(N) : "memory");
}
__device__ __forceinline__ void mma_f16(float& c0, float& c1, float& c2, float& c3,
                                        uint32_t a0, uint32_t a1, uint32_t a2, uint32_t a3,
                                        uint32_t b0, uint32_t b1) {
    asm volatile(
        "mma.sync.aligned.m16n8k16.row.col.f32.f16.f16.f32 "
        "{%0,%1,%2,%3}, {%4,%5,%6,%7}, {%8,%9}, {%0,%1,%2,%3};"
        : "+f"(c0), "+f"(c1), "+f"(c2), "+f"(c3)
        : "r"(a0), "r"(a1), "r"(a2), "r"(a3), "r"(b0), "r"(b1));
}

// ================= shared fp16 mma sweep =================
// C[128 x 128] tile: A frags (8 mt) from Af/nksA, B frags (16 nt from nb0)/nksB.
#define L_STAGE_B 32768
#define L_SMEM 69632

__device__ void mma_sweep(char* sm, const uint4* __restrict__ Af, int nksA,
                          const uint2* __restrict__ Bf, int nksB,
                          int nchunk, int nb0, float c[4][4][4]) {
    const uint32_t sb32 = smem_u32(sm);
    const int tid = threadIdx.x;
    const int wid = tid >> 5, lane = tid & 31;
    const int warpM = wid >> 2, warpN = wid & 3;

    auto load_stage = [&](int cc) {
        const int ks0 = cc * 4;
        const uint32_t base = sb32 + (cc & 1) * L_STAGE_B;
#pragma unroll
        for (int i = 0; i < 4; i++) {          // A: 1024 x 16B
            const int idx = tid + i * 256;
            const int mt = idx >> 7, rem = idx & 127;
            const int ksl = rem >> 5, ln = rem & 31;
            cp16(base + idx * 16, Af + ((mt * nksA + ks0 + ksl) * 32 + ln));
        }
#pragma unroll
        for (int i = 0; i < 8; i++) {          // B: 2048 x 8B
            const int idx = tid + i * 256;
            const int ntl = idx >> 7;
            const int ksl = (idx >> 5) & 3, ln = idx & 31;
            cp8(base + 16384 + idx * 8,
                Bf + ((size_t)(nb0 + ntl) * nksB + ks0 + ksl) * 32 + ln);
        }
        cp_commit();
    };

    load_stage(0);
    for (int cc = 0; cc < nchunk; cc++) {
        if (cc + 1 < nchunk) { load_stage(cc + 1); cp_wait<1>(); }
        else                 { cp_wait<0>(); }
        __syncthreads();
        const char* buf = sm + (cc & 1) * L_STAGE_B;
#pragma unroll
        for (int ksl = 0; ksl < 4; ksl++) {
            uint4 af[4];
            uint2 bf[4];
#pragma unroll
            for (int mi = 0; mi < 4; mi++) {
                const int mt = warpM * 4 + mi;
                af[mi] = *(const uint4*)(buf + ((mt * 4 + ksl) * 32 + lane) * 16);
            }
#pragma unroll
            for (int ni = 0; ni < 4; ni++) {
                const int nt = warpN * 4 + ni;
                bf[ni] = *(const uint2*)(buf + 16384 + ((nt * 4 + ksl) * 32 + lane) * 8);
            }
#pragma unroll
            for (int mi = 0; mi < 4; mi++)
#pragma unroll
                for (int ni = 0; ni < 4; ni++)
                    mma_f16(c[mi][ni][0], c[mi][ni][1], c[mi][ni][2], c[mi][ni][3],
                            af[mi].x, af[mi].y, af[mi].z, af[mi].w,
                            bf[ni].x, bf[ni].y);
        }
        __syncthreads();
    }
}

__device__ __forceinline__ void stage_c(char* sm, float c[4][4][4]) {
    float* st = (float*)sm;                     // 128 x 132
    const int tid = threadIdx.x;
    const int wid = tid >> 5, lane = tid & 31;
    const int warpM = wid >> 2, warpN = wid & 3;
    const int g = lane >> 2, t4 = lane & 3;
#pragma unroll
    for (int mi = 0; mi < 4; mi++) {
        const int m = warpM * 64 + mi * 16 + g;
#pragma unroll
        for (int ni = 0; ni < 4; ni++) {
            const int col = warpN * 32 + ni * 8 + 2 * t4;
            st[m * 132 + col]           = c[mi][ni][0];
            st[m * 132 + col + 1]       = c[mi][ni][1];
            st[(m + 8) * 132 + col]     = c[mi][ni][2];
            st[(m + 8) * 132 + col + 1] = c[mi][ni][3];
        }
    }
}

// ================= fp16 dual-split logits GEMM =================
__global__ void __launch_bounds__(256, 2)
logits_mma(const float* __restrict__ bias, int t) {
    extern __shared__ char sm[];
    const int tid = threadIdx.x;
    const int nb0 = blockIdx.x * 16;
    const int n0 = blockIdx.x * 128;

    float c[4][4][4];
#pragma unroll
    for (int mi = 0; mi < 4; mi++)
#pragma unroll
        for (int ni = 0; ni < 4; ni++)
#pragma unroll
            for (int r = 0; r < 4; r++) c[mi][ni][r] = 0.0f;

    mma_sweep(sm, (const uint4*)g_AfragM, NKS_M,
              (const uint2*)g_BfragM, NKS_M, NKS_M / 4, nb0, c);
#pragma unroll
    for (int mi = 0; mi < 4; mi++)
#pragma unroll
        for (int ni = 0; ni < 4; ni++)
#pragma unroll
            for (int r = 0; r < 4; r++) c[mi][ni][r] *= LO_INV;
    // hi sweep: B = hi-half of BfragM (ks 32..63) via +32*32 uint2 offset
    mma_sweep(sm, (const uint4*)g_AfragH, NKS_H,
              (const uint2*)g_BfragM + 1024, NKS_M, NKS_H / 4, nb0, c);

    stage_c(sm, c);
    __syncthreads();
    float* st = (float*)sm;
    {
        const int row = tid & 127;
        const int c0 = (tid >> 7) * 64;
        float bestv = -3.4e38f;
        int bestn = 0;
#pragma unroll 8
        for (int cc2 = 0; cc2 < 64; cc2++) {
            const int col = c0 + cc2;
            float v = st[row * 132 + col] + __ldg(&bias[n0 + col]);
            if (v > bestv) { bestv = v; bestn = n0 + col; }
        }
        atomicMax(&g_amax2[t & 1][row], amax_key(bestv, bestn));
    }
    for (int idx = tid; idx < 128 * 128; idx += 256) {
        const int m2 = idx >> 7, cc2 = idx & 127;
        g_scratch[((size_t)m2 * TT + t) * VOC + n0 + cc2] =
            st[m2 * 132 + cc2] + __ldg(&bias[n0 + cc2]);
    }
}

// ================= fp16 dual-split ka GEMM =================
// ka[by*128..+128, n0..+128] = feature-tile @ W_ienc^T + b_ienc
__global__ void __launch_bounds__(256, 2)
ka_mma(const float* __restrict__ bias) {
    extern __shared__ char sm[];
    const int tid = threadIdx.x;
    const int nb0 = blockIdx.x * 16;
    const int n0 = blockIdx.x * 128;
    const int by = blockIdx.y;

    float c[4][4][4];
#pragma unroll
    for (int mi = 0; mi < 4; mi++)
#pragma unroll
        for (int ni = 0; ni < 4; ni++)
#pragma unroll
            for (int r = 0; r < 4; r++) c[mi][ni][r] = 0.0f;

    const uint4* AfM = (const uint4*)g_AkaM + (size_t)by * 8 * NKS_M * 32;
    const uint4* AfH = (const uint4*)g_AkaH + (size_t)by * 8 * NKS_H * 32;
    mma_sweep(sm, AfM, NKS_M, (const uint2*)g_BkaM, NKS_M, NKS_M / 4, nb0, c);
#pragma unroll
    for (int mi = 0; mi < 4; mi++)
#pragma unroll
        for (int ni = 0; ni < 4; ni++)
#pragma unroll
            for (int r = 0; r < 4; r++) c[mi][ni][r] *= LO_INV;
    mma_sweep(sm, AfH, NKS_H, (const uint2*)g_BkaM + 1024, NKS_M, NKS_H / 4, nb0, c);

    stage_c(sm, c);
    __syncthreads();
    const float* st = (const float*)sm;
    for (int idx = tid; idx < 128 * 128; idx += 256) {
        const int m2 = idx >> 7, cc2 = idx & 127;
        g_ka[((size_t)by * 128 + m2) * ADIM + n0 + cc2] =
            st[m2 * 132 + cc2] + __ldg(&bias[n0 + cc2]);
    }
}

// ===== coalesced B-fragment build (shared by logits W_out and ka W_ienc) =====
// dst layout [nt][ks<64][lane][4 halves]; ks<32 -> lo_s(W[k]), ks>=32 -> hi(W[k-512])
__global__ void k_bfrag(const float* __restrict__ W, __half* __restrict__ dst,
                        size_t nslots) {
    size_t s = (size_t)blockIdx.x * 256 + threadIdx.x;
    if (s >= nslots) return;
    const int lane = (int)(s & 31);
    const int ks = (int)((s >> 5) & 63);
    const int nt = (int)(s >> 11);
    const int n = nt * 8 + (lane >> 2);
    const bool isLo = (ks < 32);
    const int k0 = (ks & 31) * 16 + (lane & 3) * 2;
    const float* Wr = W + (size_t)n * 512;
    float w0 = __ldg(Wr + k0),     w1 = __ldg(Wr + k0 + 1);
    float w8 = __ldg(Wr + k0 + 8), w9 = __ldg(Wr + k0 + 9);
    auto cv = [&](float w) -> __half {
        __half hi = __float2half(w);
        return isLo ? __float2half((w - __half2float(hi)) * LO_SCALE) : hi;
    };
    __half2* d = (__half2*)(dst + s * 4);
    d[0] = __halves2half2(cv(w0), cv(w1));
    d[1] = __halves2half2(cv(w8), cv(w9));
}

// ===== coalesced A-fragment build for feature (ka) =====
// Mixed slots: [mt<1568][ks<64][lane][8 halves]; ks<32 -> hi(feat[k]), else lo_s.
// ks<32 slots also mirrored into the H array at [mt][ks<32][lane].
__global__ void k_afragKA(const float* __restrict__ F) {
    size_t s = (size_t)blockIdx.x * 256 + threadIdx.x;
    if (s >= (size_t)KA_MT * NKS_M * 32) return;
    const int lane = (int)(s & 31);
    const int ks = (int)((s >> 5) & 63);
    const int mt = (int)(s >> 11);
    const int r = lane >> 2;
    const int c0 = (lane & 3) * 2;
    const int bk = (ks & 31) * 16;
    const bool isHi = (ks < 32);
    const int m0 = mt * 16 + r;
    const float* F0 = F + (size_t)m0 * 512 + bk;        // row r
    const float* F1 = F0 + (size_t)8 * 512;             // row r+8
    float a0 = __ldg(F0 + c0),     a1 = __ldg(F0 + c0 + 1);
    float a8 = __ldg(F0 + c0 + 8), a9 = __ldg(F0 + c0 + 9);
    float b0 = __ldg(F1 + c0),     b1 = __ldg(F1 + c0 + 1);
    float b8 = __ldg(F1 + c0 + 8), b9 = __ldg(F1 + c0 + 9);
    auto cv = [&](float w) -> __half {
        __half hi = __float2half(w);
        return isHi ? hi : __float2half((w - __half2float(hi)) * LO_SCALE);
    };
    // halves order: [r,c0],[r,c0+1],[r+8,c0],[r+8,c0+1],[r,c0+8],[r,c0+9],[r+8,c0+8],[r+8,c0+9]
    __half2 h0 = __halves2half2(cv(a0), cv(a1));
    __half2 h1 = __halves2half2(cv(b0), cv(b1));
    __half2 h2 = __halves2half2(cv(a8), cv(a9));
    __half2 h3 = __halves2half2(cv(b8), cv(b9));
    __half2* dM = (__half2*)(g_AkaM + s * 8);
    dM[0] = h0; dM[1] = h1; dM[2] = h2; dM[3] = h3;
    if (isHi) {
        __half2* dH = (__half2*)(g_AkaH + (((size_t)mt * NKS_H + ks) * 32 + lane) * 8);
        dH[0] = h0; dH[1] = h1; dH[2] = h2; dH[3] = h3;
    }
}

// ================= K-split-2 small-M GEMM (256 threads) =================
// MODE 0: C = acc + bias   MODE 1: gated ctx   MODE 2: gates+cell   MODE 4: init hn
template <int MODE>
__global__ __launch_bounds__(256)
void gemm_ks(const float* __restrict__ A, const float* __restrict__ B,
             const float* __restrict__ bias, float* __restrict__ C,
             int N, int K,
             const float* __restrict__ emb,
             const unsigned long long* __restrict__ am_rd,
             unsigned long long* __restrict__ am_clr,
             int rd_par, int wr_par) {
    __shared__ float As[2][2][32][16];
    __shared__ float Bs[2][2][32][64];
    __shared__ float red[128][8];
    const int bn = blockIdx.x * 64;
    const int bm = blockIdx.y * 16;
    const int tid = threadIdx.x;
    const int l = tid & 127;
    const int g = tid >> 7;
    const int tx = l & 15;
    const int ty = l >> 4;
    const int ar = l >> 3;
    const int ac = (l & 7) * 4;
    const int br = l >> 1;
    const int bc = (l & 1) * 16;
    const int arow = bm + ar;
    const int kbase = g * (K >> 1);

    size_t tokoff = 0;
    if (MODE == 2) tokoff = (size_t)amax_idx(am_rd[arow]) * EMBD;
    const int hn_rd = 512 + rd_par * 512;

    const float* Bp = B + (size_t)(bn + br) * K + kbase + bc;

    auto ldA4 = [&](int k0) -> float4 {
        const int kk = kbase + k0 + ac;
        if (MODE == 2) {
            const float* p;
            if (kk < 512)       p = emb + tokoff + kk;
            else if (kk < 1024) p = g_z + (size_t)arow * ZROW + (kk - 512);
            else                p = g_z + (size_t)arow * ZROW + hn_rd + (kk - 1024);
            return *(const float4*)p;
        }
        return *(const float4*)(A + (size_t)arow * K + kk);
    };

    float4 av = ldA4(0);
    float4 bv0 = *(const float4*)(Bp + 0);
    float4 bv1 = *(const float4*)(Bp + 4);
    float4 bv2 = *(const float4*)(Bp + 8);
    float4 bv3 = *(const float4*)(Bp + 12);

    float acc[2][4] = {};
    const int nk = K >> 6;
    for (int it = 0; it < nk; it++) {
        const int st = it & 1;
        As[g][st][ac + 0][ar] = av.x; As[g][st][ac + 1][ar] = av.y;
        As[g][st][ac + 2][ar] = av.z; As[g][st][ac + 3][ar] = av.w;
        Bs[g][st][bc +  0][br] = bv0.x; Bs[g][st][bc +  1][br] = bv0.y;
        Bs[g][st][bc +  2][br] = bv0.z; Bs[g][st][bc +  3][br] = bv0.w;
        Bs[g][st][bc +  4][br] = bv1.x; Bs[g][st][bc +  5][br] = bv1.y;
        Bs[g][st][bc +  6][br] = bv1.z; Bs[g][st][bc +  7][br] = bv1.w;
        Bs[g][st][bc +  8][br] = bv2.x; Bs[g][st][bc +  9][br] = bv2.y;
        Bs[g][st][bc + 10][br] = bv2.z; Bs[g][st][bc + 11][br] = bv2.w;
        Bs[g][st][bc + 12][br] = bv3.x; Bs[g][st][bc + 13][br] = bv3.y;
        Bs[g][st][bc + 14][br] = bv3.z; Bs[g][st][bc + 15][br] = bv3.w;
        __syncthreads();
        if (it + 1 < nk) {
            const int k0 = (it + 1) << 5;
            av = ldA4(k0);
            bv0 = *(const float4*)(Bp + k0);
            bv1 = *(const float4*)(Bp + k0 + 4);
            bv2 = *(const float4*)(Bp + k0 + 8);
            bv3 = *(const float4*)(Bp + k0 + 12);
        }
#pragma unroll
        for (int k = 0; k < 32; k++) {
            float a0 = As[g][st][k][2 * ty];
            float a1 = As[g][st][k][2 * ty + 1];
            float4 bv = *(const float4*)(&Bs[g][st][k][tx * 4]);
            acc[0][0] = fmaf(a0, bv.x, acc[0][0]);
            acc[0][1] = fmaf(a0, bv.y, acc[0][1]);
            acc[0][2] = fmaf(a0, bv.z, acc[0][2]);
            acc[0][3] = fmaf(a0, bv.w, acc[0][3]);
            acc[1][0] = fmaf(a1, bv.x, acc[1][0]);
            acc[1][1] = fmaf(a1, bv.y, acc[1][1]);
            acc[1][2] = fmaf(a1, bv.z, acc[1][2]);
            acc[1][3] = fmaf(a1, bv.w, acc[1][3]);
        }
    }

    if (g == 1) {
#pragma unroll
        for (int r = 0; r < 2; r++)
#pragma unroll
            for (int j = 0; j < 4; j++) red[l][r * 4 + j] = acc[r][j];
    }
    __syncthreads();
    if (g != 0) return;
#pragma unroll
    for (int r = 0; r < 2; r++)
#pragma unroll
        for (int j = 0; j < 4; j++) acc[r][j] += red[l][r * 4 + j];

    const int m0 = bm + 2 * ty;
    const int n0 = bn + 4 * tx;
#pragma unroll
    for (int r = 0; r < 2; r++) {
        const int m = m0 + r;
        if (MODE == 2) {
            const int h = n0 >> 2;
            float gi = acc[r][0] + g_bcat[n0];
            float gf = acc[r][1] + g_bcat[n0 + 1];
            float gg = acc[r][2] + g_bcat[n0 + 2];
            float go = acc[r][3] + g_bcat[n0 + 3];
            float c = sigmf(gf) * g_c[m * HDIM + h] + sigmf(gi) * tanhf(gg);
            float hn = sigmf(go) * tanhf(c);
            g_c[m * HDIM + h] = c;
            g_h[m * HDIM + h] = hn;
            g_z[m * ZROW + 512 + wr_par * 512 + h] = hn;
            put_afrag(m, h, hn);
            if (blockIdx.x == 0 && tx == 0) am_clr[m] = 0ull;
        } else {
#pragma unroll
            for (int j = 0; j < 4; j++) {
                const int n = n0 + j;
                float v = acc[r][j] + bias[n];
                if (MODE == 0) {
                    C[(size_t)m * N + n] = v;
                } else if (MODE == 1) {
                    float s = sigmf(v);
                    g_z[m * ZROW + n] = s * g_ctx[m * 512 + n];
                } else if (MODE == 4) {
                    C[(size_t)m * N + n] = v;
                    g_z[m * ZROW + 512 + n] = v;
                    put_afrag(m, n, v);
                }
            }
        }
    }
}

// ---------------- small kernels ----------------
__global__ void k_mean(const float* __restrict__ feat) {
    int b = blockIdx.x, e = threadIdx.x;
    const float* f = feat + (size_t)b * PIX * EDIM + e;
    float s = 0.0f;
    for (int p = 0; p < PIX; p++) s += f[(size_t)p * EDIM];
    g_mean[b * EDIM + e] = s * (1.0f / (float)PIX);
}

__global__ void k_x0(const int* __restrict__ captions) {
    int b = threadIdx.x;
    g_amax2[1][b] = amax_key(0.0f, captions[b * TT]);
}

__global__ void k_pack(const float* __restrict__ Wlih, const float* __restrict__ Wlhh,
                       const float* __restrict__ blih, const float* __restrict__ blhh) {
    int i = blockIdx.x * blockDim.x + threadIdx.x;
    if (i >= G4 * KP) return;
    int jp = i / KP, k = i - jp * KP;
    int h = jp >> 2, gate = jp & 3;
    int orig = gate * 512 + h;
    g_Wcat[i] = (k < 1024) ? Wlih[(size_t)orig * 1024 + k]
                           : Wlhh[(size_t)orig * 512 + (k - 1024)];
    if (k == 0) g_bcat[jp] = blih[orig] + blhh[orig];
}

__global__ __launch_bounds__(512)
void k_att(const float* __restrict__ feat, const float* __restrict__ Watt,
           const float* __restrict__ batt) {
    __shared__ float q_s[ADIM];
    __shared__ float w_s[ADIM];
    __shared__ float e_s[PIX];
    __shared__ float red[16];
    const int b = blockIdx.x, tid = threadIdx.x;
    const int warp = tid >> 5, lane = tid & 31;

    q_s[tid] = g_q[b * ADIM + tid];
    w_s[tid] = Watt[tid];
    __syncthreads();

    for (int p = warp; p < PIX; p += 16) {
        const float* kap = g_ka + ((size_t)(b * PIX + p)) * ADIM;
        float s = 0.0f;
        for (int a = lane; a < ADIM; a += 32) {
            float v = kap[a] + q_s[a];
            s += fmaxf(v, 0.0f) * w_s[a];
        }
#pragma unroll
        for (int o = 16; o; o >>= 1) s += __shfl_xor_sync(0xffffffffu, s, o);
        if (lane == 0) e_s[p] = s + batt[0];
    }
    __syncthreads();

    float m = (tid < PIX) ? e_s[tid] : -3.4e38f;
#pragma unroll
    for (int o = 16; o; o >>= 1) m = fmaxf(m, __shfl_xor_sync(0xffffffffu, m, o));
    if (lane == 0) red[warp] = m;
    __syncthreads();
    if (tid == 0) {
        float v = red[0];
        for (int i = 1; i < 16; i++) v = fmaxf(v, red[i]);
        red[0] = v;
    }
    __syncthreads();
    m = red[0];
    float ex = (tid < PIX) ? expf(e_s[tid] - m) : 0.0f;
    float ssum = ex;
#pragma unroll
    for (int o = 16; o; o >>= 1) ssum += __shfl_xor_sync(0xffffffffu, ssum, o);
    __syncthreads();
    if (lane == 0) red[warp] = ssum;
    __syncthreads();
    if (tid == 0) {
        float v = 0.0f;
        for (int i = 0; i < 16; i++) v += red[i];
        red[0] = 1.0f / v;
    }
    __syncthreads();
    if (tid < PIX) e_s[tid] = ex * red[0];
    __syncthreads();

    float acc = 0.0f;
    const float* fb = feat + (size_t)b * PIX * EDIM + tid;
    for (int p = 0; p < PIX; p++) acc = fmaf(e_s[p], fb[(size_t)p * EDIM], acc);
    g_ctx[b * EDIM + tid] = acc;
}

__global__ __launch_bounds__(256)
void k_tr(float* __restrict__ out) {
    __shared__ float sm[256 * 21];
    const int b = blockIdx.y;
    const int v0 = blockIdx.x * 256;
    const int tid = threadIdx.x;
    const float* src = g_scratch + (size_t)b * TT * VOC;
#pragma unroll
    for (int t = 0; t < TT; t++) sm[tid * 21 + t] = src[(size_t)t * VOC + v0 + tid];
    __syncthreads();
    float* ob = out + (size_t)b * VOC * TT + (size_t)v0 * TT;
    for (int e = tid; e < 256 * TT; e += 256) {
        int v = e / TT, t = e - v * TT;
        ob[e] = sm[v * 21 + t];
    }
}

// ---------------- host launch ----------------
static inline void* sym_addr(const void* symbol) {
    void* p = nullptr;
    cudaGetSymbolAddress(&p, symbol);
    return p;
}

extern "C" void kernel_launch(void* const* d_in, const int* in_sizes, int n_in,
                              void* d_out, int out_size) {
    const float* feat    = (const float*)d_in[0];
    const int*   caps    = (const int*)d_in[1];
    const float* W_ienc  = (const float*)d_in[2];
    const float* b_ienc  = (const float*)d_in[3];
    const float* W_oenc  = (const float*)d_in[4];
    const float* b_oenc  = (const float*)d_in[5];
    const float* W_att   = (const float*)d_in[6];
    const float* b_att   = (const float*)d_in[7];
    const float* W_inith = (const float*)d_in[8];
    const float* b_inith = (const float*)d_in[9];
    const float* W_initc = (const float*)d_in[10];
    const float* b_initc = (const float*)d_in[11];
    const float* W_gate  = (const float*)d_in[12];
    const float* b_gate  = (const float*)d_in[13];
    const float* embT    = (const float*)d_in[14];
    const float* W_lih   = (const float*)d_in[15];
    const float* W_lhh   = (const float*)d_in[16];
    const float* b_lih   = (const float*)d_in[17];
    const float* b_lhh   = (const float*)d_in[18];
    const float* W_out   = (const float*)d_in[19];
    const float* b_out   = (const float*)d_in[20];
    float* out = (float*)d_out;

    float* p_mean = (float*)sym_addr(g_mean);
    float* p_h    = (float*)sym_addr(g_h);
    float* p_c    = (float*)sym_addr(g_c);
    float* p_q    = (float*)sym_addr(g_q);
    float* p_ctx  = (float*)sym_addr(g_ctx);
    float* p_Wcat = (float*)sym_addr(g_Wcat);
    __half* p_BfragM = (__half*)sym_addr(g_BfragM);
    __half* p_BkaM   = (__half*)sym_addr(g_BkaM);
    unsigned long long* p_am = (unsigned long long*)sym_addr(g_amax2);

    static cudaStream_t s1 = nullptr;
    static cudaEvent_t evRoot, evK;
    if (!s1) {
        cudaFuncSetAttribute(logits_mma, cudaFuncAttributeMaxDynamicSharedMemorySize, L_SMEM);
        cudaFuncSetAttribute(ka_mma,     cudaFuncAttributeMaxDynamicSharedMemorySize, L_SMEM);
        cudaStreamCreateWithFlags(&s1, cudaStreamNonBlocking);
        cudaEventCreateWithFlags(&evRoot, cudaEventDisableTiming);
        cudaEventCreateWithFlags(&evK,    cudaEventDisableTiming);
    }

    const dim3 gsQ(ADIM / 64, BSZ / 16);   // 64 blocks
    const dim3 gsG(G4 / 64, BSZ / 16);     // 256 blocks

    // ---- side stream: fp16-split ka (frag prep + mma) ----
    cudaEventRecord(evRoot, 0);
    cudaStreamWaitEvent(s1, evRoot, 0);
    {
        size_t nA = (size_t)KA_MT * NKS_M * 32;      // 3.2M slots
        size_t nBk = (size_t)KA_NT * NKS_M * 32;     // 131K slots
        k_afragKA<<<(unsigned)((nA + 255) / 256), 256, 0, s1>>>(feat);
        k_bfrag<<<(unsigned)((nBk + 255) / 256), 256, 0, s1>>>(W_ienc, p_BkaM, nBk);
        ka_mma<<<dim3(ADIM / 128, BSZ * PIX / 128), 256, L_SMEM, s1>>>(b_ienc);
    }
    cudaEventRecord(evK, s1);

    // ---- main-stream setup ----
    k_mean<<<BSZ, 512>>>(feat);
    gemm_ks<4><<<gsQ, 256>>>(p_mean, W_inith, b_inith, p_h, HDIM, EDIM,
                             nullptr, nullptr, nullptr, 0, 0);
    gemm_ks<0><<<gsQ, 256>>>(p_mean, W_initc, b_initc, p_c, HDIM, EDIM,
                             nullptr, nullptr, nullptr, 0, 0);
    k_x0<<<1, 128>>>(caps);
    k_pack<<<(G4 * KP + 255) / 256, 256>>>(W_lih, W_lhh, b_lih, b_lhh);
    {
        size_t nB = (size_t)NT8 * NKS_M * 32;        // 8.19M slots
        k_bfrag<<<(unsigned)((nB + 255) / 256), 256>>>(W_out, p_BfragM, nB);
    }

    cudaStreamWaitEvent(0, evK, 0);   // att needs ka; rejoins s1

    // ---- T recurrent steps ----
    for (int t = 0; t < TT; t++) {
        gemm_ks<0><<<gsQ, 256>>>(p_h, W_oenc, b_oenc, p_q, ADIM, HDIM,
                                 nullptr, nullptr, nullptr, 0, 0);
        k_att<<<BSZ, 512>>>(feat, W_att, b_att);
        gemm_ks<1><<<gsQ, 256>>>(p_ctx, W_gate, b_gate, nullptr, EDIM, EDIM,
                                 nullptr, nullptr, nullptr, 0, 0);
        gemm_ks<2><<<gsG, 256>>>(nullptr, p_Wcat, nullptr, nullptr, G4, KP, embT,
                                 p_am + ((t + 1) & 1) * BSZ, p_am + (t & 1) * BSZ,
                                 t & 1, (t + 1) & 1);
        logits_mma<<<VOC / 128, 256, L_SMEM>>>(b_out, t);
    }

    k_tr<<<dim3(VOC / 256, BSZ), 256>>>(out);
}